// round 1
// baseline (speedup 1.0000x reference)
#include <cuda_runtime.h>

#define N_BATCH 1024
#define T_STEPS 64
#define D_IN    512
#define H_DIM   1024
#define G4      (4 * H_DIM)   // 4096
#define L16     16

// ---------------- scratch (static device globals; no allocation) ------------
__device__ float g_P [(size_t)N_BATCH * L16 * G4];     // 256 MB: P[n,l,:] = Af[n,:,l] @ Wattn
__device__ float g_At[(size_t)N_BATCH * L16 * H_DIM];  //  64 MB: transposed Af for the P GEMM
__device__ float g_h [(size_t)N_BATCH * H_DIM];        //   4 MB
__device__ float g_c [(size_t)N_BATCH * H_DIM];        //   4 MB
__device__ float g_a [(size_t)N_BATCH * G4];           //  16 MB: pre-activation gates

// ---------------- f32x2 helpers (Blackwell packed fp32 FMA) -----------------
__device__ __forceinline__ void ffma2(unsigned long long &d,
                                      unsigned long long a,
                                      unsigned long long b) {
    asm("fma.rn.f32x2 %0, %1, %2, %0;" : "+l"(d) : "l"(a), "l"(b));
}

// ---------------- prep: transpose Af, init h0 = c0 = mean --------------------
__global__ void prep_kernel(const float* __restrict__ Af,
                            float* __restrict__ At,
                            float* __restrict__ h0,
                            float* __restrict__ c0) {
    int idx = blockIdx.x * blockDim.x + threadIdx.x;   // n*H + h
    int n = idx >> 10;
    int h = idx & (H_DIM - 1);
    const float4* src = (const float4*)(Af + (size_t)idx * 16);
    float4 r0 = src[0], r1 = src[1], r2 = src[2], r3 = src[3];
    float v[16] = {r0.x, r0.y, r0.z, r0.w, r1.x, r1.y, r1.z, r1.w,
                   r2.x, r2.y, r2.z, r2.w, r3.x, r3.y, r3.z, r3.w};
    float s = 0.f;
#pragma unroll
    for (int l = 0; l < 16; l++) s += v[l];
    float m = s * (1.0f / 16.0f);
    h0[idx] = m;
    c0[idx] = m;
#pragma unroll
    for (int l = 0; l < 16; l++)
        At[((size_t)(n * 16 + l) << 10) + h] = v[l];
}

// ---------------- GEMM: C (+)= A(M,K; row stride lda) @ B(K,Nc) (+ bias) -----
// 128x128 block tile, BK=16, 256 threads, 8x8 per thread, FFMA2 microkernel.
template <bool ACC, bool BIAS>
__global__ void __launch_bounds__(256, 2)
sgemm_kernel(const float* __restrict__ A, int lda,
             const float* __restrict__ B,
             const float* __restrict__ bias,
             float* __restrict__ C,
             int M, int K, int Nc) {
    __shared__ float As2[16][256];   // A values duplicated in pairs for LDS.64 broadcast
    __shared__ float Bs[16][128];

    const int tid = threadIdx.x;
    const int bm = blockIdx.y * 128;
    const int bn = blockIdx.x * 128;
    const int tx = (tid & 15) * 8;   // column offset of 8-wide micro tile
    const int ty = (tid >> 4) * 8;   // row offset of 8-tall micro tile

    const int ar = tid >> 2;         // 0..63  (A tile row loader)
    const int ac = (tid & 3) * 4;    // 0,4,8,12
    const int br = tid >> 5;         // 0..7   (B tile row loader)
    const int bc = (tid & 31) * 4;

    unsigned long long acc[8][4];
#pragma unroll
    for (int i = 0; i < 8; i++)
#pragma unroll
        for (int q = 0; q < 4; q++) acc[i][q] = 0ull;

    const float* Abase = A + (size_t)bm * lda;
    const float* Bbase = B + bn;

    for (int k0 = 0; k0 < K; k0 += 16) {
#pragma unroll
        for (int i = 0; i < 2; i++) {
            int r = ar + i * 64;
            float4 va = *(const float4*)(Abase + (size_t)r * lda + k0 + ac);
            *(float2*)&As2[ac + 0][2 * r] = make_float2(va.x, va.x);
            *(float2*)&As2[ac + 1][2 * r] = make_float2(va.y, va.y);
            *(float2*)&As2[ac + 2][2 * r] = make_float2(va.z, va.z);
            *(float2*)&As2[ac + 3][2 * r] = make_float2(va.w, va.w);
        }
#pragma unroll
        for (int i = 0; i < 2; i++) {
            int r = br + i * 8;
            *(float4*)&Bs[r][bc] = *(const float4*)(Bbase + (size_t)(k0 + r) * Nc + bc);
        }
        __syncthreads();
#pragma unroll
        for (int kk = 0; kk < 16; kk++) {
            unsigned long long a2[8], b2[4];
            const unsigned long long* ap = (const unsigned long long*)&As2[kk][2 * ty];
            const unsigned long long* bp = (const unsigned long long*)&Bs[kk][tx];
#pragma unroll
            for (int i = 0; i < 8; i++) a2[i] = ap[i];
#pragma unroll
            for (int q = 0; q < 4; q++) b2[q] = bp[q];
#pragma unroll
            for (int i = 0; i < 8; i++)
#pragma unroll
                for (int q = 0; q < 4; q++)
                    ffma2(acc[i][q], a2[i], b2[q]);
        }
        __syncthreads();
    }

#pragma unroll
    for (int i = 0; i < 8; i++) {
        float* Crow = C + (size_t)(bm + ty + i) * Nc + bn + tx;
#pragma unroll
        for (int q = 0; q < 4; q++) {
            float lo, hi;
            asm("mov.b64 {%0, %1}, %2;" : "=f"(lo), "=f"(hi) : "l"(acc[i][q]));
            if (BIAS) {
                lo += bias[bn + tx + 2 * q];
                hi += bias[bn + tx + 2 * q + 1];
            }
            if (ACC) {
                float2 old = *(const float2*)(Crow + 2 * q);
                lo += old.x;
                hi += old.y;
            }
            *(float2*)(Crow + 2 * q) = make_float2(lo, hi);
        }
    }
}

// ---------------- per-step attention: scores -> softmax -> a = P^T w ---------
__global__ void attn_kernel(const float* __restrict__ Af,
                            const float* __restrict__ h,
                            const float* __restrict__ P,
                            float* __restrict__ a) {
    __shared__ float h_sh[H_DIM];
    __shared__ float red[16];
    __shared__ float w_sh[16];

    const int n = blockIdx.x;
    const int tid = threadIdx.x;  // 256 threads

    ((float4*)h_sh)[tid] = ((const float4*)(h + (size_t)n * H_DIM))[tid];
    if (tid < 16) red[tid] = 0.f;
    __syncthreads();

    float part[16];
#pragma unroll
    for (int l = 0; l < 16; l++) part[l] = 0.f;

    const float* Abase = Af + (size_t)n * (H_DIM * 16);
#pragma unroll
    for (int k = 0; k < 4; k++) {
        int hh = tid + k * 256;
        float hv = h_sh[hh];
        const float4* row = (const float4*)(Abase + (size_t)hh * 16);
        float4 r0 = row[0], r1 = row[1], r2 = row[2], r3 = row[3];
        part[0]  += hv * r0.x; part[1]  += hv * r0.y; part[2]  += hv * r0.z; part[3]  += hv * r0.w;
        part[4]  += hv * r1.x; part[5]  += hv * r1.y; part[6]  += hv * r1.z; part[7]  += hv * r1.w;
        part[8]  += hv * r2.x; part[9]  += hv * r2.y; part[10] += hv * r2.z; part[11] += hv * r2.w;
        part[12] += hv * r3.x; part[13] += hv * r3.y; part[14] += hv * r3.z; part[15] += hv * r3.w;
    }
#pragma unroll
    for (int l = 0; l < 16; l++) {
        float v = part[l];
        v += __shfl_down_sync(0xffffffffu, v, 16);
        v += __shfl_down_sync(0xffffffffu, v, 8);
        v += __shfl_down_sync(0xffffffffu, v, 4);
        v += __shfl_down_sync(0xffffffffu, v, 2);
        v += __shfl_down_sync(0xffffffffu, v, 1);
        if ((tid & 31) == 0) atomicAdd(&red[l], v);
    }
    __syncthreads();

    if (tid == 0) {
        const float scale = 0.03125f;  // 1/sqrt(1024)
        float s[16], mx = -1e30f;
#pragma unroll
        for (int l = 0; l < 16; l++) { s[l] = red[l] * scale; mx = fmaxf(mx, s[l]); }
        float sum = 0.f;
#pragma unroll
        for (int l = 0; l < 16; l++) { s[l] = expf(s[l] - mx); sum += s[l]; }
        float inv = 1.f / sum;
#pragma unroll
        for (int l = 0; l < 16; l++) w_sh[l] = s[l] * inv;
    }
    __syncthreads();

    float w[16];
#pragma unroll
    for (int l = 0; l < 16; l++) w[l] = w_sh[l];

    const float* Pbase = P + (size_t)n * 16 * G4;
    float* arow = a + (size_t)n * G4;
    for (int j = tid; j < G4; j += 256) {
        float acc = 0.f;
#pragma unroll
        for (int l = 0; l < 16; l++) acc += w[l] * Pbase[(size_t)l * G4 + j];
        arow[j] = acc;
    }
}

// ---------------- LSTM gate elementwise -------------------------------------
__global__ void lstm_kernel(const float* __restrict__ a,
                            float* __restrict__ c,
                            float* __restrict__ h,
                            float* __restrict__ out, int t) {
    int idx = blockIdx.x * blockDim.x + threadIdx.x;  // n*H + j
    int n = idx >> 10;
    int j = idx & (H_DIM - 1);
    const float* ar = a + (size_t)n * G4;
    float ai = ar[j];
    float af = ar[H_DIM + j];
    float ao = ar[2 * H_DIM + j];
    float ag = ar[3 * H_DIM + j];
    float i_ = 1.f / (1.f + expf(-ai));
    float f_ = 1.f / (1.f + expf(-af));
    float o_ = 1.f / (1.f + expf(-ao));
    float g_ = tanhf(ag);
    float cn = f_ * c[idx] + i_ * g_;
    float hn = o_ * tanhf(cn);
    c[idx] = cn;
    h[idx] = hn;
    out[((size_t)n * T_STEPS + t) * H_DIM + j] = hn;
}

// ---------------- launch ------------------------------------------------------
extern "C" void kernel_launch(void* const* d_in, const int* in_sizes, int n_in,
                              void* d_out, int out_size) {
    const float* x     = (const float*)d_in[0];  // (N, T, D)
    const float* Af    = (const float*)d_in[1];  // (N, H, 16)
    const float* Wx    = (const float*)d_in[2];  // (D, 4H)
    const float* Wh    = (const float*)d_in[3];  // (H, 4H)
    const float* Wattn = (const float*)d_in[4];  // (H, 4H)
    const float* b     = (const float*)d_in[5];  // (4H)
    float* out = (float*)d_out;                  // (N, T, H)

    float *P, *At, *h, *c, *a;
    cudaGetSymbolAddress((void**)&P,  g_P);
    cudaGetSymbolAddress((void**)&At, g_At);
    cudaGetSymbolAddress((void**)&h,  g_h);
    cudaGetSymbolAddress((void**)&c,  g_c);
    cudaGetSymbolAddress((void**)&a,  g_a);

    // prep: At transpose + h0/c0
    prep_kernel<<<(N_BATCH * H_DIM) / 256, 256>>>(Af, At, h, c);

    // P = At @ Wattn   (one-time, parallel: removes attn@Wattn from the recurrence)
    {
        dim3 grid(G4 / 128, (N_BATCH * L16) / 128);
        sgemm_kernel<false, false><<<grid, 256>>>(At, H_DIM, Wattn, nullptr, P,
                                                  N_BATCH * L16, H_DIM, G4);
    }

    dim3 gstep(G4 / 128, N_BATCH / 128);
    for (int t = 0; t < T_STEPS; t++) {
        // a = sum_l w_l * P[n,l,:]
        attn_kernel<<<N_BATCH, 256>>>(Af, h, P, a);
        // a += x_t @ Wx + b   (x rows strided by T*D)
        sgemm_kernel<true, true><<<gstep, 256>>>(x + (size_t)t * D_IN, T_STEPS * D_IN,
                                                 Wx, b, a, N_BATCH, D_IN, G4);
        // a += h @ Wh
        sgemm_kernel<true, false><<<gstep, 256>>>(h, H_DIM, Wh, nullptr, a,
                                                  N_BATCH, H_DIM, G4);
        // gates -> c, h, out[:, t, :]
        lstm_kernel<<<(N_BATCH * H_DIM) / 256, 256>>>(a, c, h, out, t);
    }
}

// round 2
// speedup vs baseline: 1.1577x; 1.1577x over previous
#include <cuda_runtime.h>

#define N_BATCH 1024
#define T_STEPS 64
#define D_IN    512
#define H_DIM   1024
#define G4      (4 * H_DIM)   // 4096
#define L16     16

// ---------------- scratch (static device globals; no allocation) ------------
__device__ float g_XW[(size_t)N_BATCH * T_STEPS * G4];  //   1 GB: x@Wx + b for all t
__device__ float g_P [(size_t)N_BATCH * L16 * G4];      // 256 MB: P[n,l,:] = Af[n,:,l] @ Wattn
__device__ float g_At[(size_t)N_BATCH * L16 * H_DIM];   //  64 MB
__device__ float g_h [(size_t)N_BATCH * H_DIM];
__device__ float g_c [(size_t)N_BATCH * H_DIM];
__device__ float g_a [(size_t)N_BATCH * G4];

// ---------------- f32x2 helpers ----------------------------------------------
__device__ __forceinline__ void ffma2(unsigned long long &d,
                                      unsigned long long a,
                                      unsigned long long b) {
    asm("fma.rn.f32x2 %0, %1, %2, %0;" : "+l"(d) : "l"(a), "l"(b));
}

// ---------------- prep: transpose Af, init h0 = c0 = mean --------------------
__global__ void prep_kernel(const float* __restrict__ Af,
                            float* __restrict__ At,
                            float* __restrict__ h0,
                            float* __restrict__ c0) {
    int idx = blockIdx.x * blockDim.x + threadIdx.x;   // n*H + h
    int n = idx >> 10;
    int h = idx & (H_DIM - 1);
    const float4* src = (const float4*)(Af + (size_t)idx * 16);
    float4 r0 = src[0], r1 = src[1], r2 = src[2], r3 = src[3];
    float v[16] = {r0.x, r0.y, r0.z, r0.w, r1.x, r1.y, r1.z, r1.w,
                   r2.x, r2.y, r2.z, r2.w, r3.x, r3.y, r3.z, r3.w};
    float s = 0.f;
#pragma unroll
    for (int l = 0; l < 16; l++) s += v[l];
    float m = s * (1.0f / 16.0f);
    h0[idx] = m;
    c0[idx] = m;
#pragma unroll
    for (int l = 0; l < 16; l++)
        At[((size_t)(n * 16 + l) << 10) + h] = v[l];
}

// ---------------- GEMM: C (+)= A(M,K; row stride lda) @ B(K,Nc) (+ bias) -----
// 128x128 tile, BK=8, 256 threads, 8x8 per thread, FFMA2, double-buffered smem.
template <bool ACC, bool BIAS>
__global__ void __launch_bounds__(256, 2)
sgemm_kernel(const float* __restrict__ A, int lda,
             const float* __restrict__ B,
             const float* __restrict__ bias,
             float* __restrict__ C,
             int K, int Nc) {
    __shared__ float As2[2][8][256];   // A duplicated in pairs for LDS.64 broadcast
    __shared__ float Bs[2][8][128];

    const int tid = threadIdx.x;
    const int bm = blockIdx.y * 128;
    const int bn = blockIdx.x * 128;
    const int tx = (tid & 15) * 8;
    const int ty = (tid >> 4) * 8;

    const int ar = tid >> 1;          // 0..127 (A loader: one float4 per thread)
    const int ac = (tid & 1) * 4;     // 0 or 4
    const int br = tid >> 5;          // 0..7   (B loader: one float4 per thread)
    const int bc = (tid & 31) * 4;

    const float* Aptr = A + (size_t)(bm + ar) * lda + ac;
    const float* Bptr = B + (size_t)br * Nc + bn + bc;

    unsigned long long acc[8][4];
#pragma unroll
    for (int i = 0; i < 8; i++)
#pragma unroll
        for (int q = 0; q < 4; q++) acc[i][q] = 0ull;

    float4 pa = *(const float4*)Aptr;
    float4 pb = *(const float4*)Bptr;

    // store tile 0
    *(float2*)&As2[0][ac + 0][2 * ar] = make_float2(pa.x, pa.x);
    *(float2*)&As2[0][ac + 1][2 * ar] = make_float2(pa.y, pa.y);
    *(float2*)&As2[0][ac + 2][2 * ar] = make_float2(pa.z, pa.z);
    *(float2*)&As2[0][ac + 3][2 * ar] = make_float2(pa.w, pa.w);
    *(float4*)&Bs[0][br][bc] = pb;
    __syncthreads();

    const int KT = K / 8;
    int buf = 0;
    for (int kt = 0; kt < KT; kt++) {
        if (kt + 1 < KT) {
            pa = *(const float4*)(Aptr + (kt + 1) * 8);
            pb = *(const float4*)(Bptr + (size_t)(kt + 1) * 8 * Nc);
        }
#pragma unroll
        for (int kk = 0; kk < 8; kk++) {
            unsigned long long a2[8], b2[4];
            const unsigned long long* ap = (const unsigned long long*)&As2[buf][kk][2 * ty];
            const unsigned long long* bp = (const unsigned long long*)&Bs[buf][kk][tx];
#pragma unroll
            for (int i = 0; i < 8; i++) a2[i] = ap[i];
#pragma unroll
            for (int q = 0; q < 4; q++) b2[q] = bp[q];
#pragma unroll
            for (int i = 0; i < 8; i++)
#pragma unroll
                for (int q = 0; q < 4; q++)
                    ffma2(acc[i][q], a2[i], b2[q]);
        }
        if (kt + 1 < KT) {
            int nb = buf ^ 1;
            *(float2*)&As2[nb][ac + 0][2 * ar] = make_float2(pa.x, pa.x);
            *(float2*)&As2[nb][ac + 1][2 * ar] = make_float2(pa.y, pa.y);
            *(float2*)&As2[nb][ac + 2][2 * ar] = make_float2(pa.z, pa.z);
            *(float2*)&As2[nb][ac + 3][2 * ar] = make_float2(pa.w, pa.w);
            *(float4*)&Bs[nb][br][bc] = pb;
        }
        __syncthreads();
        buf ^= 1;
    }

#pragma unroll
    for (int i = 0; i < 8; i++) {
        float* Crow = C + (size_t)(bm + ty + i) * Nc + bn + tx;
#pragma unroll
        for (int q = 0; q < 4; q++) {
            float lo, hi;
            asm("mov.b64 {%0, %1}, %2;" : "=f"(lo), "=f"(hi) : "l"(acc[i][q]));
            if (BIAS) {
                lo += bias[bn + tx + 2 * q];
                hi += bias[bn + tx + 2 * q + 1];
            }
            if (ACC) {
                float2 old = *(const float2*)(Crow + 2 * q);
                lo += old.x;
                hi += old.y;
            }
            *(float2*)(Crow + 2 * q) = make_float2(lo, hi);
        }
    }
}

// ------- per-step attention: scores -> softmax -> a = P^T w + XW[:,t,:] ------
__global__ void attn_kernel(const float* __restrict__ Af,
                            const float* __restrict__ h,
                            const float* __restrict__ P,
                            const float* __restrict__ XW, int t,
                            float* __restrict__ a) {
    __shared__ float h_sh[H_DIM];
    __shared__ float red[16];
    __shared__ float w_sh[16];

    const int n = blockIdx.x;
    const int tid = threadIdx.x;  // 256 threads

    ((float4*)h_sh)[tid] = ((const float4*)(h + (size_t)n * H_DIM))[tid];
    if (tid < 16) red[tid] = 0.f;
    __syncthreads();

    float part[16];
#pragma unroll
    for (int l = 0; l < 16; l++) part[l] = 0.f;

    const float* Abase = Af + (size_t)n * (H_DIM * 16);
#pragma unroll
    for (int k = 0; k < 4; k++) {
        int hh = tid + k * 256;
        float hv = h_sh[hh];
        const float4* row = (const float4*)(Abase + (size_t)hh * 16);
        float4 r0 = row[0], r1 = row[1], r2 = row[2], r3 = row[3];
        part[0]  += hv * r0.x; part[1]  += hv * r0.y; part[2]  += hv * r0.z; part[3]  += hv * r0.w;
        part[4]  += hv * r1.x; part[5]  += hv * r1.y; part[6]  += hv * r1.z; part[7]  += hv * r1.w;
        part[8]  += hv * r2.x; part[9]  += hv * r2.y; part[10] += hv * r2.z; part[11] += hv * r2.w;
        part[12] += hv * r3.x; part[13] += hv * r3.y; part[14] += hv * r3.z; part[15] += hv * r3.w;
    }
#pragma unroll
    for (int l = 0; l < 16; l++) {
        float v = part[l];
        v += __shfl_down_sync(0xffffffffu, v, 16);
        v += __shfl_down_sync(0xffffffffu, v, 8);
        v += __shfl_down_sync(0xffffffffu, v, 4);
        v += __shfl_down_sync(0xffffffffu, v, 2);
        v += __shfl_down_sync(0xffffffffu, v, 1);
        if ((tid & 31) == 0) atomicAdd(&red[l], v);
    }
    __syncthreads();

    if (tid == 0) {
        const float scale = 0.03125f;  // 1/sqrt(1024)
        float s[16], mx = -1e30f;
#pragma unroll
        for (int l = 0; l < 16; l++) { s[l] = red[l] * scale; mx = fmaxf(mx, s[l]); }
        float sum = 0.f;
#pragma unroll
        for (int l = 0; l < 16; l++) { s[l] = expf(s[l] - mx); sum += s[l]; }
        float inv = 1.f / sum;
#pragma unroll
        for (int l = 0; l < 16; l++) w_sh[l] = s[l] * inv;
    }
    __syncthreads();

    float w[16];
#pragma unroll
    for (int l = 0; l < 16; l++) w[l] = w_sh[l];

    const float4* Pb  = (const float4*)(P + (size_t)n * L16 * G4);
    const float4* xw4 = (const float4*)(XW + ((size_t)n * T_STEPS + t) * G4);
    float4* ar4 = (float4*)(a + (size_t)n * G4);
#pragma unroll 4
    for (int j = tid; j < G4 / 4; j += 256) {
        float4 acc = xw4[j];
#pragma unroll
        for (int l = 0; l < 16; l++) {
            float4 p = Pb[(size_t)l * (G4 / 4) + j];
            acc.x += w[l] * p.x;
            acc.y += w[l] * p.y;
            acc.z += w[l] * p.z;
            acc.w += w[l] * p.w;
        }
        ar4[j] = acc;
    }
}

// ---------------- LSTM gate elementwise -------------------------------------
__global__ void lstm_kernel(const float* __restrict__ a,
                            float* __restrict__ c,
                            float* __restrict__ h,
                            float* __restrict__ out, int t) {
    int idx = blockIdx.x * blockDim.x + threadIdx.x;  // n*H + j
    int n = idx >> 10;
    int j = idx & (H_DIM - 1);
    const float* ar = a + (size_t)n * G4;
    float ai = ar[j];
    float af = ar[H_DIM + j];
    float ao = ar[2 * H_DIM + j];
    float ag = ar[3 * H_DIM + j];
    float i_ = 1.f / (1.f + expf(-ai));
    float f_ = 1.f / (1.f + expf(-af));
    float o_ = 1.f / (1.f + expf(-ao));
    float g_ = tanhf(ag);
    float cn = f_ * c[idx] + i_ * g_;
    float hn = o_ * tanhf(cn);
    c[idx] = cn;
    h[idx] = hn;
    out[((size_t)n * T_STEPS + t) * H_DIM + j] = hn;
}

// ---------------- launch ------------------------------------------------------
extern "C" void kernel_launch(void* const* d_in, const int* in_sizes, int n_in,
                              void* d_out, int out_size) {
    const float* x     = (const float*)d_in[0];  // (N, T, D)
    const float* Af    = (const float*)d_in[1];  // (N, H, 16)
    const float* Wx    = (const float*)d_in[2];  // (D, 4H)
    const float* Wh    = (const float*)d_in[3];  // (H, 4H)
    const float* Wattn = (const float*)d_in[4];  // (H, 4H)
    const float* b     = (const float*)d_in[5];  // (4H)
    float* out = (float*)d_out;                  // (N, T, H)

    float *XW, *P, *At, *h, *c, *a;
    cudaGetSymbolAddress((void**)&XW, g_XW);
    cudaGetSymbolAddress((void**)&P,  g_P);
    cudaGetSymbolAddress((void**)&At, g_At);
    cudaGetSymbolAddress((void**)&h,  g_h);
    cudaGetSymbolAddress((void**)&c,  g_c);
    cudaGetSymbolAddress((void**)&a,  g_a);

    // prep: At transpose + h0/c0
    prep_kernel<<<(N_BATCH * H_DIM) / 256, 256>>>(Af, At, h, c);

    // XW = x @ Wx + b for ALL timesteps (one big parallel GEMM, M = N*T = 65536)
    {
        dim3 grid(G4 / 128, (N_BATCH * T_STEPS) / 128);
        sgemm_kernel<false, true><<<grid, 256>>>(x, D_IN, Wx, b, XW, D_IN, G4);
    }

    // P = At @ Wattn (removes attn@Wattn from the recurrence)
    {
        dim3 grid(G4 / 128, (N_BATCH * L16) / 128);
        sgemm_kernel<false, false><<<grid, 256>>>(At, H_DIM, Wattn, nullptr, P, H_DIM, G4);
    }

    dim3 gstep(G4 / 128, N_BATCH / 128);
    for (int t = 0; t < T_STEPS; t++) {
        // a = XW[:, t, :] + sum_l w_l * P[n,l,:]
        attn_kernel<<<N_BATCH, 256>>>(Af, h, P, XW, t, a);
        // a += h @ Wh
        sgemm_kernel<true, false><<<gstep, 256>>>(h, H_DIM, Wh, nullptr, a, H_DIM, G4);
        // gates -> c, h, out[:, t, :]
        lstm_kernel<<<(N_BATCH * H_DIM) / 256, 256>>>(a, c, h, out, t);
    }
}

// round 3
// speedup vs baseline: 1.1596x; 1.0017x over previous
#include <cuda_runtime.h>

#define N_BATCH 1024
#define T_STEPS 64
#define D_IN    512
#define H_DIM   1024
#define G4      (4 * H_DIM)   // 4096
#define L16     16

// ---------------- scratch (static device globals; no allocation) ------------
__device__ float g_XW[(size_t)N_BATCH * T_STEPS * G4];  //   1 GB: x@Wx + b for all t
__device__ float g_P [(size_t)N_BATCH * L16 * G4];      // 256 MB: P[n,l,:] = Af[n,:,l] @ Wattn
__device__ float g_At[(size_t)N_BATCH * L16 * H_DIM];   //  64 MB
__device__ float g_h [(size_t)N_BATCH * H_DIM];
__device__ float g_c [(size_t)N_BATCH * H_DIM];
__device__ float g_a [(size_t)N_BATCH * G4];

// ---------------- f32x2 helpers ----------------------------------------------
__device__ __forceinline__ void ffma2(unsigned long long &d,
                                      unsigned long long a,
                                      unsigned long long b) {
    asm("fma.rn.f32x2 %0, %1, %2, %0;" : "+l"(d) : "l"(a), "l"(b));
}

// ---------------- prep: transpose Af, init h0 = c0 = mean --------------------
__global__ void prep_kernel(const float* __restrict__ Af,
                            float* __restrict__ At,
                            float* __restrict__ h0,
                            float* __restrict__ c0) {
    int idx = blockIdx.x * blockDim.x + threadIdx.x;   // n*H + h
    int n = idx >> 10;
    int h = idx & (H_DIM - 1);
    const float4* src = (const float4*)(Af + (size_t)idx * 16);
    float4 r0 = src[0], r1 = src[1], r2 = src[2], r3 = src[3];
    float v[16] = {r0.x, r0.y, r0.z, r0.w, r1.x, r1.y, r1.z, r1.w,
                   r2.x, r2.y, r2.z, r2.w, r3.x, r3.y, r3.z, r3.w};
    float s = 0.f;
#pragma unroll
    for (int l = 0; l < 16; l++) s += v[l];
    float m = s * (1.0f / 16.0f);
    h0[idx] = m;
    c0[idx] = m;
#pragma unroll
    for (int l = 0; l < 16; l++)
        At[((size_t)(n * 16 + l) << 10) + h] = v[l];
}

// ---------------- GEMM: C (+)= A(M,K; row stride lda) @ B(K,Nc) (+ bias) -----
// 128x128 tile, BK=8, 256 threads, 8x8 per thread, FFMA2, double-buffered smem.
template <bool ACC, bool BIAS>
__global__ void __launch_bounds__(256, 2)
sgemm_kernel(const float* __restrict__ A, int lda,
             const float* __restrict__ B,
             const float* __restrict__ bias,
             float* __restrict__ C,
             int K, int Nc) {
    __shared__ float As2[2][8][256];   // A duplicated in pairs for LDS.64 broadcast
    __shared__ float Bs[2][8][128];

    const int tid = threadIdx.x;
    const int bm = blockIdx.y * 128;
    const int bn = blockIdx.x * 128;
    const int tx = (tid & 15) * 8;
    const int ty = (tid >> 4) * 8;

    const int ar = tid >> 1;          // 0..127 (A loader: one float4 per thread)
    const int ac = (tid & 1) * 4;     // 0 or 4
    const int br = tid >> 5;          // 0..7   (B loader: one float4 per thread)
    const int bc = (tid & 31) * 4;

    const float* Aptr = A + (size_t)(bm + ar) * lda + ac;
    const float* Bptr = B + (size_t)br * Nc + bn + bc;

    unsigned long long acc[8][4];
#pragma unroll
    for (int i = 0; i < 8; i++)
#pragma unroll
        for (int q = 0; q < 4; q++) acc[i][q] = 0ull;

    float4 pa = *(const float4*)Aptr;
    float4 pb = *(const float4*)Bptr;

    // store tile 0
    *(float2*)&As2[0][ac + 0][2 * ar] = make_float2(pa.x, pa.x);
    *(float2*)&As2[0][ac + 1][2 * ar] = make_float2(pa.y, pa.y);
    *(float2*)&As2[0][ac + 2][2 * ar] = make_float2(pa.z, pa.z);
    *(float2*)&As2[0][ac + 3][2 * ar] = make_float2(pa.w, pa.w);
    *(float4*)&Bs[0][br][bc] = pb;
    __syncthreads();

    const int KT = K / 8;
    int buf = 0;
    for (int kt = 0; kt < KT; kt++) {
        if (kt + 1 < KT) {
            pa = *(const float4*)(Aptr + (kt + 1) * 8);
            pb = *(const float4*)(Bptr + (size_t)(kt + 1) * 8 * Nc);
        }
#pragma unroll
        for (int kk = 0; kk < 8; kk++) {
            unsigned long long a2[8], b2[4];
            const unsigned long long* ap = (const unsigned long long*)&As2[buf][kk][2 * ty];
            const unsigned long long* bp = (const unsigned long long*)&Bs[buf][kk][tx];
#pragma unroll
            for (int i = 0; i < 8; i++) a2[i] = ap[i];
#pragma unroll
            for (int q = 0; q < 4; q++) b2[q] = bp[q];
#pragma unroll
            for (int i = 0; i < 8; i++)
#pragma unroll
                for (int q = 0; q < 4; q++)
                    ffma2(acc[i][q], a2[i], b2[q]);
        }
        if (kt + 1 < KT) {
            int nb = buf ^ 1;
            *(float2*)&As2[nb][ac + 0][2 * ar] = make_float2(pa.x, pa.x);
            *(float2*)&As2[nb][ac + 1][2 * ar] = make_float2(pa.y, pa.y);
            *(float2*)&As2[nb][ac + 2][2 * ar] = make_float2(pa.z, pa.z);
            *(float2*)&As2[nb][ac + 3][2 * ar] = make_float2(pa.w, pa.w);
            *(float4*)&Bs[nb][br][bc] = pb;
        }
        __syncthreads();
        buf ^= 1;
    }

#pragma unroll
    for (int i = 0; i < 8; i++) {
        float* Crow = C + (size_t)(bm + ty + i) * Nc + bn + tx;
#pragma unroll
        for (int q = 0; q < 4; q++) {
            float lo, hi;
            asm("mov.b64 {%0, %1}, %2;" : "=f"(lo), "=f"(hi) : "l"(acc[i][q]));
            if (BIAS) {
                lo += bias[bn + tx + 2 * q];
                hi += bias[bn + tx + 2 * q + 1];
            }
            if (ACC) {
                float2 old = *(const float2*)(Crow + 2 * q);
                lo += old.x;
                hi += old.y;
            }
            *(float2*)(Crow + 2 * q) = make_float2(lo, hi);
        }
    }
}

// ------- per-step attention: scores -> softmax -> a = P^T w + XW[:,t,:] ------
__global__ void attn_kernel(const float* __restrict__ Af,
                            const float* __restrict__ h,
                            const float* __restrict__ P,
                            const float* __restrict__ XW, int t,
                            float* __restrict__ a) {
    __shared__ float h_sh[H_DIM];
    __shared__ float red[16];
    __shared__ float w_sh[16];

    const int n = blockIdx.x;
    const int tid = threadIdx.x;  // 256 threads

    ((float4*)h_sh)[tid] = ((const float4*)(h + (size_t)n * H_DIM))[tid];
    if (tid < 16) red[tid] = 0.f;
    __syncthreads();

    float part[16];
#pragma unroll
    for (int l = 0; l < 16; l++) part[l] = 0.f;

    const float* Abase = Af + (size_t)n * (H_DIM * 16);
#pragma unroll
    for (int k = 0; k < 4; k++) {
        int hh = tid + k * 256;
        float hv = h_sh[hh];
        const float4* row = (const float4*)(Abase + (size_t)hh * 16);
        float4 r0 = row[0], r1 = row[1], r2 = row[2], r3 = row[3];
        part[0]  += hv * r0.x; part[1]  += hv * r0.y; part[2]  += hv * r0.z; part[3]  += hv * r0.w;
        part[4]  += hv * r1.x; part[5]  += hv * r1.y; part[6]  += hv * r1.z; part[7]  += hv * r1.w;
        part[8]  += hv * r2.x; part[9]  += hv * r2.y; part[10] += hv * r2.z; part[11] += hv * r2.w;
        part[12] += hv * r3.x; part[13] += hv * r3.y; part[14] += hv * r3.z; part[15] += hv * r3.w;
    }
#pragma unroll
    for (int l = 0; l < 16; l++) {
        float v = part[l];
        v += __shfl_down_sync(0xffffffffu, v, 16);
        v += __shfl_down_sync(0xffffffffu, v, 8);
        v += __shfl_down_sync(0xffffffffu, v, 4);
        v += __shfl_down_sync(0xffffffffu, v, 2);
        v += __shfl_down_sync(0xffffffffu, v, 1);
        if ((tid & 31) == 0) atomicAdd(&red[l], v);
    }
    __syncthreads();

    if (tid == 0) {
        const float scale = 0.03125f;  // 1/sqrt(1024)
        float s[16], mx = -1e30f;
#pragma unroll
        for (int l = 0; l < 16; l++) { s[l] = red[l] * scale; mx = fmaxf(mx, s[l]); }
        float sum = 0.f;
#pragma unroll
        for (int l = 0; l < 16; l++) { s[l] = expf(s[l] - mx); sum += s[l]; }
        float inv = 1.f / sum;
#pragma unroll
        for (int l = 0; l < 16; l++) w_sh[l] = s[l] * inv;
    }
    __syncthreads();

    float w[16];
#pragma unroll
    for (int l = 0; l < 16; l++) w[l] = w_sh[l];

    const float4* Pb  = (const float4*)(P + (size_t)n * L16 * G4);
    const float4* xw4 = (const float4*)(XW + ((size_t)n * T_STEPS + t) * G4);
    float4* ar4 = (float4*)(a + (size_t)n * G4);
#pragma unroll 4
    for (int j = tid; j < G4 / 4; j += 256) {
        float4 acc = xw4[j];
#pragma unroll
        for (int l = 0; l < 16; l++) {
            float4 p = Pb[(size_t)l * (G4 / 4) + j];
            acc.x += w[l] * p.x;
            acc.y += w[l] * p.y;
            acc.z += w[l] * p.z;
            acc.w += w[l] * p.w;
        }
        ar4[j] = acc;
    }
}

// ---------------- LSTM gate elementwise -------------------------------------
__global__ void lstm_kernel(const float* __restrict__ a,
                            float* __restrict__ c,
                            float* __restrict__ h,
                            float* __restrict__ out, int t) {
    int idx = blockIdx.x * blockDim.x + threadIdx.x;  // n*H + j
    int n = idx >> 10;
    int j = idx & (H_DIM - 1);
    const float* ar = a + (size_t)n * G4;
    float ai = ar[j];
    float af = ar[H_DIM + j];
    float ao = ar[2 * H_DIM + j];
    float ag = ar[3 * H_DIM + j];
    float i_ = 1.f / (1.f + expf(-ai));
    float f_ = 1.f / (1.f + expf(-af));
    float o_ = 1.f / (1.f + expf(-ao));
    float g_ = tanhf(ag);
    float cn = f_ * c[idx] + i_ * g_;
    float hn = o_ * tanhf(cn);
    c[idx] = cn;
    h[idx] = hn;
    out[((size_t)n * T_STEPS + t) * H_DIM + j] = hn;
}

// ---------------- launch ------------------------------------------------------
extern "C" void kernel_launch(void* const* d_in, const int* in_sizes, int n_in,
                              void* d_out, int out_size) {
    const float* x     = (const float*)d_in[0];  // (N, T, D)
    const float* Af    = (const float*)d_in[1];  // (N, H, 16)
    const float* Wx    = (const float*)d_in[2];  // (D, 4H)
    const float* Wh    = (const float*)d_in[3];  // (H, 4H)
    const float* Wattn = (const float*)d_in[4];  // (H, 4H)
    const float* b     = (const float*)d_in[5];  // (4H)
    float* out = (float*)d_out;                  // (N, T, H)

    float *XW, *P, *At, *h, *c, *a;
    cudaGetSymbolAddress((void**)&XW, g_XW);
    cudaGetSymbolAddress((void**)&P,  g_P);
    cudaGetSymbolAddress((void**)&At, g_At);
    cudaGetSymbolAddress((void**)&h,  g_h);
    cudaGetSymbolAddress((void**)&c,  g_c);
    cudaGetSymbolAddress((void**)&a,  g_a);

    // prep: At transpose + h0/c0
    prep_kernel<<<(N_BATCH * H_DIM) / 256, 256>>>(Af, At, h, c);

    // XW = x @ Wx + b for ALL timesteps (one big parallel GEMM, M = N*T = 65536)
    {
        dim3 grid(G4 / 128, (N_BATCH * T_STEPS) / 128);
        sgemm_kernel<false, true><<<grid, 256>>>(x, D_IN, Wx, b, XW, D_IN, G4);
    }

    // P = At @ Wattn (removes attn@Wattn from the recurrence)
    {
        dim3 grid(G4 / 128, (N_BATCH * L16) / 128);
        sgemm_kernel<false, false><<<grid, 256>>>(At, H_DIM, Wattn, nullptr, P, H_DIM, G4);
    }

    dim3 gstep(G4 / 128, N_BATCH / 128);
    for (int t = 0; t < T_STEPS; t++) {
        // a = XW[:, t, :] + sum_l w_l * P[n,l,:]
        attn_kernel<<<N_BATCH, 256>>>(Af, h, P, XW, t, a);
        // a += h @ Wh
        sgemm_kernel<true, false><<<gstep, 256>>>(h, H_DIM, Wh, nullptr, a, H_DIM, G4);
        // gates -> c, h, out[:, t, :]
        lstm_kernel<<<(N_BATCH * H_DIM) / 256, 256>>>(a, c, h, out, t);
    }
}

// round 5
// speedup vs baseline: 2.7351x; 2.3586x over previous
#include <cuda_runtime.h>
#include <cuda_bf16.h>
#include <cstdint>

#define N_BATCH 1024
#define T_STEPS 64
#define D_IN    512
#define H_DIM   1024
#define G4      4096
#define K2      2048
typedef __nv_bfloat16 bf16;

__device__ float g_XW [(size_t)N_BATCH * T_STEPS * G4];
__device__ bf16  g_xh [(size_t)N_BATCH * T_STEPS * D_IN];
__device__ bf16  g_xl [(size_t)N_BATCH * T_STEPS * D_IN];
__device__ bf16  g_Wxh[(size_t)G4 * D_IN];   // Wx^T hi (4096 x 512, K-major)
__device__ bf16  g_Wxl[(size_t)G4 * D_IN];
__device__ bf16  g_Wch[(size_t)G4 * K2];     // [Wh;Wattn]^T hi (4096 x 2048)
__device__ bf16  g_Wcl[(size_t)G4 * K2];
__device__ bf16  g_A2h[(size_t)N_BATCH * K2];  // [h | attn] hi
__device__ bf16  g_A2l[(size_t)N_BATCH * K2];
__device__ float g_h [(size_t)N_BATCH * H_DIM];
__device__ float g_c [(size_t)N_BATCH * H_DIM];
__device__ float g_hw[(size_t)N_BATCH * G4];

// ---- helpers ----
__device__ __forceinline__ uint32_t s2u(const void* p) {
    uint32_t a;
    asm("{.reg .u64 t; cvta.to.shared.u64 t, %1; cvt.u32.u64 %0, t;}" : "=r"(a) : "l"(p));
    return a;
}
#define SW128(o) ((o) ^ (((o) >> 3) & 0x70))

__device__ __forceinline__ void cpa(uint32_t s, const void* g) {
    asm volatile("cp.async.cg.shared.global [%0], [%1], 16;" :: "r"(s), "l"(g));
}
#define CP_COMMIT() asm volatile("cp.async.commit_group;" ::: "memory")
#define CP_WAIT1()  asm volatile("cp.async.wait_group 1;" ::: "memory")

__device__ __forceinline__ void mma16816(float* c, const uint32_t* a, const uint32_t* b) {
    asm volatile("mma.sync.aligned.m16n8k16.row.col.f32.bf16.bf16.f32 "
        "{%0,%1,%2,%3}, {%4,%5,%6,%7}, {%8,%9}, {%0,%1,%2,%3};"
        : "+f"(c[0]), "+f"(c[1]), "+f"(c[2]), "+f"(c[3])
        : "r"(a[0]), "r"(a[1]), "r"(a[2]), "r"(a[3]), "r"(b[0]), "r"(b[1]));
}
__device__ __forceinline__ void ldsm4(uint32_t* r, uint32_t a) {
    asm volatile("ldmatrix.sync.aligned.m8n8.x4.shared.b16 {%0,%1,%2,%3}, [%4];"
        : "=r"(r[0]), "=r"(r[1]), "=r"(r[2]), "=r"(r[3]) : "r"(a));
}
__device__ __forceinline__ void ldsm2(uint32_t* r, uint32_t a) {
    asm volatile("ldmatrix.sync.aligned.m8n8.x2.shared.b16 {%0,%1}, [%2];"
        : "=r"(r[0]), "=r"(r[1]) : "r"(a));
}
__device__ __forceinline__ void bsplit(float x, bf16& hi, bf16& lo) {
    hi = __float2bfloat16(x);
    lo = __float2bfloat16(x - __bfloat162float(hi));
}

// ===== GEMM: C[M,Nc] = splitA[M,K](lda) @ splitB[Nc,K](ldb)^T (+bias) ========
// 128x128 tile, BK=64, 8 warps (2Mx4N), cp.async 3-stage, SW128 smem, HMMA.
// smem stage: Ah 16K | Al 16K | Bh 16K | Bl 16K = 64KB; 3 stages = 192KB.
#define GSMEM (3 * 65536)
template <bool BIAS>
__global__ void __launch_bounds__(256, 1)
gemm_kernel(const bf16* __restrict__ Ah, const bf16* __restrict__ Al, int lda,
            const bf16* __restrict__ Bh, const bf16* __restrict__ Bl, int ldb,
            const float* __restrict__ bias, float* __restrict__ C, int K, int Nc) {
    extern __shared__ char smx[];
    const uint32_t sb = s2u(smx);
    const int tid = threadIdx.x, wid = tid >> 5, lane = tid & 31;
    const int bm = blockIdx.y * 128, bn = blockIdx.x * 128;
    const int wm = (wid >> 2) * 64, wn = (wid & 3) * 32;

    // loader: chunk u = tid + i*256 -> row = tid/8 + 32i, col16 = tid%8
    uint32_t so[4];
#pragma unroll
    for (int i = 0; i < 4; i++)
        so[i] = SW128((uint32_t)(((tid >> 3) + i * 32) * 128 + (tid & 7) * 16));

    const int KT = K / 64;
    float acc[4][4][4];
#pragma unroll
    for (int mt = 0; mt < 4; mt++)
#pragma unroll
        for (int nt = 0; nt < 4; nt++)
#pragma unroll
            for (int v = 0; v < 4; v++) acc[mt][nt][v] = 0.f;

    auto load_stage = [&](int kt, int st) {
        if (kt < KT) {
            uint32_t s0 = sb + st * 65536;
#pragma unroll
            for (int i = 0; i < 4; i++) {
                int r = (tid >> 3) + i * 32;
                size_t ga = (size_t)(bm + r) * lda + kt * 64 + (tid & 7) * 8;
                size_t gb = (size_t)(bn + r) * ldb + kt * 64 + (tid & 7) * 8;
                cpa(s0 + so[i],         Ah + ga);
                cpa(s0 + 16384 + so[i], Al + ga);
                cpa(s0 + 32768 + so[i], Bh + gb);
                cpa(s0 + 49152 + so[i], Bl + gb);
            }
        }
        CP_COMMIT();
    };

    load_stage(0, 0);
    load_stage(1, 1);

    const int arow  = wm + (lane & 7) + ((lane >> 3) & 1) * 8;
    const int acolb = ((lane >> 4) & 1) * 16;
    const int brow  = wn + (lane & 7);
    const int bcolb = ((lane >> 3) & 1) * 16;

    for (int kt = 0; kt < KT; kt++) {
        CP_WAIT1();
        __syncthreads();
        load_stage(kt + 2, (kt + 2) % 3);

        uint32_t s0 = sb + (kt % 3) * 65536;
#pragma unroll
        for (int ks = 0; ks < 4; ks++) {
            uint32_t ah[4][4], al[4][4], bh[4][2], bl[4][2];
#pragma unroll
            for (int mt = 0; mt < 4; mt++) {
                uint32_t off = SW128((uint32_t)((arow + mt * 16) * 128 + ks * 32 + acolb));
                ldsm4(ah[mt], s0 + off);
                ldsm4(al[mt], s0 + 16384 + off);
            }
#pragma unroll
            for (int nt = 0; nt < 4; nt++) {
                uint32_t off = SW128((uint32_t)((brow + nt * 8) * 128 + ks * 32 + bcolb));
                ldsm2(bh[nt], s0 + 32768 + off);
                ldsm2(bl[nt], s0 + 49152 + off);
            }
#pragma unroll
            for (int mt = 0; mt < 4; mt++)
#pragma unroll
                for (int nt = 0; nt < 4; nt++) {
                    mma16816(acc[mt][nt], ah[mt], bh[nt]);
                    mma16816(acc[mt][nt], ah[mt], bl[nt]);
                    mma16816(acc[mt][nt], al[mt], bh[nt]);
                }
        }
        __syncthreads();
    }

    const int q = lane >> 2, i2 = (lane & 3) * 2;
#pragma unroll
    for (int mt = 0; mt < 4; mt++) {
        int row0 = bm + wm + mt * 16 + q;
#pragma unroll
        for (int nt = 0; nt < 4; nt++) {
            int col = bn + wn + nt * 8 + i2;
            float2 v0 = make_float2(acc[mt][nt][0], acc[mt][nt][1]);
            float2 v1 = make_float2(acc[mt][nt][2], acc[mt][nt][3]);
            if (BIAS) {
                float2 bb = *(const float2*)(bias + col);
                v0.x += bb.x; v0.y += bb.y; v1.x += bb.x; v1.y += bb.y;
            }
            *(float2*)(C + (size_t)row0 * Nc + col)       = v0;
            *(float2*)(C + (size_t)(row0 + 8) * Nc + col) = v1;
        }
    }
}

// ---- prep: h0=c0=mean(Af), h splits into A2 cols [0,1024) -------------------
__global__ void prep_kernel(const float* __restrict__ Af, float* h0, float* c0,
                            bf16* A2h, bf16* A2l) {
    int idx = blockIdx.x * blockDim.x + threadIdx.x;
    int n = idx >> 10, hh = idx & (H_DIM - 1);
    const float4* src = (const float4*)(Af + (size_t)idx * 16);
    float s = 0.f;
#pragma unroll
    for (int q = 0; q < 4; q++) { float4 r = src[q]; s += r.x + r.y + r.z + r.w; }
    float m = s * 0.0625f;
    h0[idx] = m; c0[idx] = m;
    bf16 hi, lo; bsplit(m, hi, lo);
    A2h[(size_t)n * K2 + hh] = hi; A2l[(size_t)n * K2 + hh] = lo;
}

__global__ void splitx_kernel(const float* __restrict__ x, bf16* xh, bf16* xl) {
    int i = blockIdx.x * blockDim.x + threadIdx.x;
    bf16 hi, lo; bsplit(x[i], hi, lo);
    xh[i] = hi; xl[i] = lo;
}

__global__ void twx_kernel(const float* __restrict__ Wx, bf16* th, bf16* tl) {
    int i = blockIdx.x * blockDim.x + threadIdx.x;   // n*512 + k
    int n = i >> 9, k = i & 511;
    bf16 hi, lo; bsplit(Wx[(size_t)k * G4 + n], hi, lo);
    th[i] = hi; tl[i] = lo;
}

__global__ void twc_kernel(const float* __restrict__ Wh, const float* __restrict__ Wa,
                           bf16* th, bf16* tl) {
    int i = blockIdx.x * blockDim.x + threadIdx.x;   // n*2048 + k
    int n = i >> 11, k = i & 2047;
    float v = (k < H_DIM) ? Wh[(size_t)k * G4 + n] : Wa[(size_t)(k - H_DIM) * G4 + n];
    bf16 hi, lo; bsplit(v, hi, lo);
    th[i] = hi; tl[i] = lo;
}

// ---- attention: scores(h,Af) -> softmax -> attn splits into A2 cols [1024,2048)
__global__ void attn_kernel(const float* __restrict__ Af, const float* __restrict__ h,
                            bf16* A2h, bf16* A2l) {
    __shared__ float h_sh[H_DIM];
    __shared__ float red[16];
    __shared__ float w_sh[16];
    const int n = blockIdx.x, tid = threadIdx.x;

    ((float4*)h_sh)[tid] = ((const float4*)(h + (size_t)n * H_DIM))[tid];
    if (tid < 16) red[tid] = 0.f;
    __syncthreads();

    float part[16];
#pragma unroll
    for (int l = 0; l < 16; l++) part[l] = 0.f;
    const float* Ab = Af + (size_t)n * (H_DIM * 16);
    float4 rows[4][4];
#pragma unroll
    for (int k = 0; k < 4; k++) {
        int hh = tid + k * 256;
        float hv = h_sh[hh];
        const float4* row = (const float4*)(Ab + (size_t)hh * 16);
#pragma unroll
        for (int q = 0; q < 4; q++) rows[k][q] = row[q];
#pragma unroll
        for (int q = 0; q < 4; q++) {
            part[4 * q + 0] += hv * rows[k][q].x;
            part[4 * q + 1] += hv * rows[k][q].y;
            part[4 * q + 2] += hv * rows[k][q].z;
            part[4 * q + 3] += hv * rows[k][q].w;
        }
    }
#pragma unroll
    for (int l = 0; l < 16; l++) {
        float v = part[l];
        v += __shfl_down_sync(~0u, v, 16);
        v += __shfl_down_sync(~0u, v, 8);
        v += __shfl_down_sync(~0u, v, 4);
        v += __shfl_down_sync(~0u, v, 2);
        v += __shfl_down_sync(~0u, v, 1);
        if ((tid & 31) == 0) atomicAdd(&red[l], v);
    }
    __syncthreads();
    if (tid == 0) {
        float s[16], mx = -1e30f, sum = 0.f;
#pragma unroll
        for (int l = 0; l < 16; l++) { s[l] = red[l] * 0.03125f; mx = fmaxf(mx, s[l]); }
#pragma unroll
        for (int l = 0; l < 16; l++) { s[l] = expf(s[l] - mx); sum += s[l]; }
        float inv = 1.f / sum;
#pragma unroll
        for (int l = 0; l < 16; l++) w_sh[l] = s[l] * inv;
    }
    __syncthreads();
    float w[16];
#pragma unroll
    for (int l = 0; l < 16; l++) w[l] = w_sh[l];
#pragma unroll
    for (int k = 0; k < 4; k++) {
        int hh = tid + k * 256;
        float acc = 0.f;
#pragma unroll
        for (int q = 0; q < 4; q++) {
            acc += w[4 * q + 0] * rows[k][q].x + w[4 * q + 1] * rows[k][q].y
                 + w[4 * q + 2] * rows[k][q].z + w[4 * q + 3] * rows[k][q].w;
        }
        bf16 hi, lo; bsplit(acc, hi, lo);
        A2h[(size_t)n * K2 + H_DIM + hh] = hi;
        A2l[(size_t)n * K2 + H_DIM + hh] = lo;
    }
}

// ---- LSTM gates: a = hw + XW[:,t,:]; update c,h; emit h splits + out ---------
__global__ void lstm_kernel(const float* __restrict__ hw, const float* __restrict__ XW,
                            float* __restrict__ c, float* __restrict__ h,
                            bf16* A2h, bf16* A2l, float* __restrict__ out, int t) {
    int idx = blockIdx.x * blockDim.x + threadIdx.x;
    int n = idx >> 10, j = idx & (H_DIM - 1);
    const float* hr = hw + (size_t)n * G4;
    const float* xr = XW + ((size_t)n * T_STEPS + t) * G4;
    float ai = hr[j] + xr[j];
    float af = hr[H_DIM + j] + xr[H_DIM + j];
    float ao = hr[2 * H_DIM + j] + xr[2 * H_DIM + j];
    float ag = hr[3 * H_DIM + j] + xr[3 * H_DIM + j];
    float i_ = 1.f / (1.f + expf(-ai));
    float f_ = 1.f / (1.f + expf(-af));
    float o_ = 1.f / (1.f + expf(-ao));
    float g_ = tanhf(ag);
    float cn = f_ * c[idx] + i_ * g_;
    float hn = o_ * tanhf(cn);
    c[idx] = cn; h[idx] = hn;
    bf16 hi, lo; bsplit(hn, hi, lo);
    A2h[(size_t)n * K2 + j] = hi;
    A2l[(size_t)n * K2 + j] = lo;
    out[((size_t)n * T_STEPS + t) * H_DIM + j] = hn;
}

extern "C" void kernel_launch(void* const* d_in, const int* in_sizes, int n_in,
                              void* d_out, int out_size) {
    const float* x     = (const float*)d_in[0];
    const float* Af    = (const float*)d_in[1];
    const float* Wx    = (const float*)d_in[2];
    const float* Wh    = (const float*)d_in[3];
    const float* Wattn = (const float*)d_in[4];
    const float* b     = (const float*)d_in[5];
    float* out = (float*)d_out;

    float *XW, *h, *c, *hw;
    bf16 *xh, *xl, *Wxh, *Wxl, *Wch, *Wcl, *A2h, *A2l;
    cudaGetSymbolAddress((void**)&XW, g_XW);
    cudaGetSymbolAddress((void**)&xh, g_xh);   cudaGetSymbolAddress((void**)&xl, g_xl);
    cudaGetSymbolAddress((void**)&Wxh, g_Wxh); cudaGetSymbolAddress((void**)&Wxl, g_Wxl);
    cudaGetSymbolAddress((void**)&Wch, g_Wch); cudaGetSymbolAddress((void**)&Wcl, g_Wcl);
    cudaGetSymbolAddress((void**)&A2h, g_A2h); cudaGetSymbolAddress((void**)&A2l, g_A2l);
    cudaGetSymbolAddress((void**)&h, g_h);     cudaGetSymbolAddress((void**)&c, g_c);
    cudaGetSymbolAddress((void**)&hw, g_hw);

    cudaFuncSetAttribute(gemm_kernel<true>,  cudaFuncAttributeMaxDynamicSharedMemorySize, GSMEM);
    cudaFuncSetAttribute(gemm_kernel<false>, cudaFuncAttributeMaxDynamicSharedMemorySize, GSMEM);

    prep_kernel<<<(N_BATCH * H_DIM) / 256, 256>>>(Af, h, c, A2h, A2l);
    splitx_kernel<<<(N_BATCH * T_STEPS * D_IN) / 256, 256>>>(x, xh, xl);
    twx_kernel<<<(G4 * D_IN) / 256, 256>>>(Wx, Wxh, Wxl);
    twc_kernel<<<(G4 * K2) / 256, 256>>>(Wh, Wattn, Wch, Wcl);

    // XW = x @ Wx + b for all t  (M = N*T = 65536)
    {
        dim3 grid(G4 / 128, (N_BATCH * T_STEPS) / 128);
        gemm_kernel<true><<<grid, 256, GSMEM>>>(xh, xl, D_IN, Wxh, Wxl, D_IN, b, XW, D_IN, G4);
    }

    dim3 gstep(G4 / 128, N_BATCH / 128);
    for (int t = 0; t < T_STEPS; t++) {
        attn_kernel<<<N_BATCH, 256>>>(Af, h, A2h, A2l);
        gemm_kernel<false><<<gstep, 256, GSMEM>>>(A2h, A2l, K2, Wch, Wcl, K2, nullptr, hw, K2, G4);
        lstm_kernel<<<(N_BATCH * H_DIM) / 256, 256>>>(hw, XW, c, h, A2h, A2l, out, t);
    }
}